// round 1
// baseline (speedup 1.0000x reference)
#include <cuda_runtime.h>
#include <cstdint>

// ---------------------------------------------------------------------------
// MultiHeadAttn: conv3x3(q/k/v) -> 16-head attention over channels -> Wo proj
// B=8, C=1024 (tokens), HW=32x32 (features: 16 heads x 64), fp32 throughout.
// ---------------------------------------------------------------------------

#define BATCH 8
#define CDIM  1024
#define POS   1024   // 32*32 spatial = feature dim
#define NHEAD 16
#define HDIM  64

// Scratch (device globals: allocation inside kernel_launch is forbidden)
__device__ float g_Qc[BATCH * CDIM * POS];
__device__ float g_Kc[BATCH * CDIM * POS];
__device__ float g_Vc[BATCH * CDIM * POS];
__device__ float g_Oc[BATCH * CDIM * POS];

// ===========================================================================
// Conv3x3 (SAME, cross-correlation, NCHW/OIHW) as implicit GEMM.
// Grid: (16 co-tiles, 16 row-pairs, 8 batch). Block 256.
// Tile: 64 co x 64 pos (pos tile = image rows 2*by, 2*by+1).
// Thread (ty,tx) in 16x16: 4 co x (2 rows x 2 cols) = 16 outputs.
// ===========================================================================
#define CK 4
__global__ __launch_bounds__(256, 4)
void conv3x3_kernel(const float* __restrict__ x, const float* __restrict__ W,
                    const float* __restrict__ bias, float* __restrict__ y)
{
    __shared__ float xs[CK][4][34];   // rows 2*by-1..2*by+2, cols -1..32
    __shared__ float ws[CK][64][9];

    const int tid = threadIdx.x;
    const int co0 = blockIdx.x * 64;
    const int by  = blockIdx.y;       // output rows 2*by, 2*by+1
    const int b   = blockIdx.z;
    const int ty = tid >> 4, tx = tid & 15;

    float acc[4][4];
#pragma unroll
    for (int i = 0; i < 4; i++)
#pragma unroll
        for (int j = 0; j < 4; j++) acc[i][j] = 0.f;

    const float* xb = x + (size_t)b * CDIM * POS;

    for (int ci0 = 0; ci0 < CDIM; ci0 += CK) {
        // --- stage x halo tile: CK x 4 rows x 34 cols ---
        for (int idx = tid; idx < CK * 136; idx += 256) {
            int ck = idx / 136, rem = idx - ck * 136;
            int lr = rem / 34,  lx  = rem - lr * 34;
            int gy = 2 * by + lr - 1, gx = lx - 1;
            float v = 0.f;
            if ((unsigned)gy < 32u && (unsigned)gx < 32u)
                v = xb[(size_t)(ci0 + ck) * 1024 + gy * 32 + gx];
            xs[ck][lr][lx] = v;
        }
        // --- stage weights: CK x 64 co x 9 ---
        for (int idx = tid; idx < CK * 576; idx += 256) {
            int ck = idx / 576, rem = idx - ck * 576;
            int co = rem / 9,   k   = rem - co * 9;
            ws[ck][co][k] = W[(size_t)(co0 + co) * 9216 + (size_t)(ci0 + ck) * 9 + k];
        }
        __syncthreads();

#pragma unroll
        for (int ck = 0; ck < CK; ck++) {
            // x registers: 4 rows x 4 cols covering 2x2 outputs' 3x3 taps
            float xr[4][4];
#pragma unroll
            for (int lr = 0; lr < 4; lr++)
#pragma unroll
                for (int lc = 0; lc < 4; lc++)
                    xr[lr][lc] = xs[ck][lr][tx * 2 + lc];

#pragma unroll
            for (int i = 0; i < 4; i++) {
                float w[9];
#pragma unroll
                for (int k = 0; k < 9; k++) w[k] = ws[ck][ty * 4 + i][k];
#pragma unroll
                for (int orow = 0; orow < 2; orow++)
#pragma unroll
                    for (int oc = 0; oc < 2; oc++) {
                        float s = acc[i][orow * 2 + oc];
#pragma unroll
                        for (int ky = 0; ky < 3; ky++)
#pragma unroll
                            for (int kx = 0; kx < 3; kx++)
                                s += w[ky * 3 + kx] * xr[orow + ky][oc + kx];
                        acc[i][orow * 2 + oc] = s;
                    }
            }
        }
        __syncthreads();
    }

#pragma unroll
    for (int i = 0; i < 4; i++) {
        int co = co0 + ty * 4 + i;
        float bv = bias[co];
#pragma unroll
        for (int orow = 0; orow < 2; orow++)
#pragma unroll
            for (int oc = 0; oc < 2; oc++) {
                int pos = (2 * by + orow) * 32 + tx * 2 + oc;
                y[((size_t)b * CDIM + co) * POS + pos] = acc[i][orow * 2 + oc] + bv;
            }
    }
}

// ===========================================================================
// Flash-style attention over channels.
// qh[b,h,t,d] = conv_out[b, t, h*64+d]; S = (Q Kt)/8 masked by mask[b,t,s];
// softmax over s; O = P V written to g_Oc[b, t, h*64+d].
// Grid: (16 t-tiles, 16 heads, 8 batch). Block 256. Dynamic smem 71424 B.
// ===========================================================================
#define SP 68   // padded row stride (floats); 68*4B keeps float4 alignment
#define ATTN_SMEM_BYTES ((4 * 64 * SP + 3 * 64 + 64 * 4) * 4)

__global__ __launch_bounds__(256, 3)
void attn_kernel(const float* __restrict__ Q, const float* __restrict__ K,
                 const float* __restrict__ V, const int* __restrict__ mask,
                 float* __restrict__ O)
{
    extern __shared__ float sm[];
    float* Qs   = sm;                 // [64 d][SP]  Qs[d][r], prescaled by 1/8
    float* Ks   = Qs + 64 * SP;       // [64 d][SP]  Ks[d][s]
    float* Vs   = Ks + 64 * SP;       // [64 s][SP]  Vs[s][dd]
    float* Ss   = Vs + 64 * SP;       // [64 s][SP]  Ss[s][r] (mask, then S, then P)
    float* mrow = Ss + 64 * SP;       // [64]
    float* lrow = mrow + 64;          // [64]
    float* frow = lrow + 64;          // [64]
    float* pbuf = frow + 64;          // [64][4]

    const int tid = threadIdx.x;
    const int t0 = blockIdx.x * 64;
    const int h  = blockIdx.y;
    const int b  = blockIdx.z;
    const int ty = tid >> 4, tx = tid & 15;
    const int h64 = h * 64;
    const size_t base  = (size_t)b * CDIM * POS;
    const size_t mbase = (size_t)b * CDIM * POS;   // mask [b][t][s]

    // Load Q tile (prescaled): Qs[d][r]
    for (int idx = tid; idx < 4096; idx += 256) {
        int r = idx >> 6, d = idx & 63;
        Qs[d * SP + r] = Q[base + (size_t)(t0 + r) * 1024 + h64 + d] * 0.125f;
    }
    if (tid < 64) { mrow[tid] = -3.0e38f; lrow[tid] = 0.f; frow[tid] = 1.f; }

    float oacc[4][4];
#pragma unroll
    for (int i = 0; i < 4; i++)
#pragma unroll
        for (int j = 0; j < 4; j++) oacc[i][j] = 0.f;

    const int rr   = tid & 63;   // softmax: row handled
    const int part = tid >> 6;   // softmax: 16-col chunk

    for (int s0 = 0; s0 < 1024; s0 += 64) {
        __syncthreads();  // (A) protect Ks/Vs/Ss from previous iteration's reads
        // Stage K, V, and mask (mask bits parked in Ss[c][r])
        for (int idx = tid; idx < 4096; idx += 256) {
            int s = idx >> 6, d = idx & 63;
            size_t g = base + (size_t)(s0 + s) * 1024 + h64 + d;
            Ks[d * SP + s] = K[g];
            Vs[s * SP + d] = V[g];
            int mm = mask[mbase + (size_t)(t0 + s) * 1024 + s0 + d];  // s=row, d=col
            Ss[d * SP + s] = __int_as_float(mm);
        }
        __syncthreads();  // (B)

        // Phase A: S = Q Kt. Thread covers rows tx*4.., cols ty*4..
        {
            const int ra = tx * 4, ca = ty * 4;
            float sacc[4][4];
#pragma unroll
            for (int i = 0; i < 4; i++)
#pragma unroll
                for (int j = 0; j < 4; j++) sacc[i][j] = 0.f;
#pragma unroll 8
            for (int d = 0; d < 64; d++) {
                float4 q4 = *(const float4*)(Qs + d * SP + ra);
                float4 k4 = *(const float4*)(Ks + d * SP + ca);
                sacc[0][0] += q4.x * k4.x; sacc[0][1] += q4.x * k4.y;
                sacc[0][2] += q4.x * k4.z; sacc[0][3] += q4.x * k4.w;
                sacc[1][0] += q4.y * k4.x; sacc[1][1] += q4.y * k4.y;
                sacc[1][2] += q4.y * k4.z; sacc[1][3] += q4.y * k4.w;
                sacc[2][0] += q4.z * k4.x; sacc[2][1] += q4.z * k4.y;
                sacc[2][2] += q4.z * k4.z; sacc[2][3] += q4.z * k4.w;
                sacc[3][0] += q4.w * k4.x; sacc[3][1] += q4.w * k4.y;
                sacc[3][2] += q4.w * k4.z; sacc[3][3] += q4.w * k4.w;
            }
            // Apply mask (bits already at the exact cells we own) and store S
#pragma unroll
            for (int j = 0; j < 4; j++) {
                float* cell = Ss + (ca + j) * SP + ra;
                float4 sv;
                sv.x = (__float_as_int(cell[0]) == 0) ? -1e9f : sacc[0][j];
                sv.y = (__float_as_int(cell[1]) == 0) ? -1e9f : sacc[1][j];
                sv.z = (__float_as_int(cell[2]) == 0) ? -1e9f : sacc[2][j];
                sv.w = (__float_as_int(cell[3]) == 0) ? -1e9f : sacc[3][j];
                *(float4*)cell = sv;
            }
        }
        __syncthreads();  // (C)

        // Phase B: online softmax bookkeeping
        {
            float pm = -3.0e38f;
#pragma unroll
            for (int j = 0; j < 16; j++)
                pm = fmaxf(pm, Ss[(part * 16 + j) * SP + rr]);
            pbuf[rr * 4 + part] = pm;
        }
        __syncthreads();  // (D)
        if (tid < 64) {
            float bm = fmaxf(fmaxf(pbuf[tid * 4 + 0], pbuf[tid * 4 + 1]),
                             fmaxf(pbuf[tid * 4 + 2], pbuf[tid * 4 + 3]));
            float mnew = fmaxf(mrow[tid], bm);
            frow[tid] = __expf(mrow[tid] - mnew);
            mrow[tid] = mnew;
        }
        __syncthreads();  // (E)
        {
            float mr = mrow[rr];
            float ps = 0.f;
#pragma unroll
            for (int j = 0; j < 16; j++) {
                int s = part * 16 + j;
                float p = __expf(Ss[s * SP + rr] - mr);
                Ss[s * SP + rr] = p;
                ps += p;
            }
            pbuf[rr * 4 + part] = ps;
        }
        __syncthreads();  // (F)
        if (tid < 64) {
            lrow[tid] = lrow[tid] * frow[tid] +
                        pbuf[tid * 4 + 0] + pbuf[tid * 4 + 1] +
                        pbuf[tid * 4 + 2] + pbuf[tid * 4 + 3];
        }
        // Rescale accumulators by this block's correction factor
        {
            const int r0 = ty * 4;
#pragma unroll
            for (int i = 0; i < 4; i++) {
                float f = frow[r0 + i];
#pragma unroll
                for (int j = 0; j < 4; j++) oacc[i][j] *= f;
            }
        }
        __syncthreads();  // (G)

        // Phase C: O += P V. Thread covers rows ty*4.., cols tx*4..
        {
            const int r0 = ty * 4, c0 = tx * 4;
#pragma unroll 8
            for (int s = 0; s < 64; s++) {
                float4 p4 = *(const float4*)(Ss + s * SP + r0);
                float4 v4 = *(const float4*)(Vs + s * SP + c0);
                oacc[0][0] += p4.x * v4.x; oacc[0][1] += p4.x * v4.y;
                oacc[0][2] += p4.x * v4.z; oacc[0][3] += p4.x * v4.w;
                oacc[1][0] += p4.y * v4.x; oacc[1][1] += p4.y * v4.y;
                oacc[1][2] += p4.y * v4.z; oacc[1][3] += p4.y * v4.w;
                oacc[2][0] += p4.z * v4.x; oacc[2][1] += p4.z * v4.y;
                oacc[2][2] += p4.z * v4.z; oacc[2][3] += p4.z * v4.w;
                oacc[3][0] += p4.w * v4.x; oacc[3][1] += p4.w * v4.y;
                oacc[3][2] += p4.w * v4.z; oacc[3][3] += p4.w * v4.w;
            }
        }
    }
    __syncthreads();

    // Finalize: divide by row sums, write out
    {
        const int r0 = ty * 4, c0 = tx * 4;
#pragma unroll
        for (int i = 0; i < 4; i++) {
            float inv = 1.0f / lrow[r0 + i];
            size_t o = base + (size_t)(t0 + r0 + i) * 1024 + h64 + c0;
#pragma unroll
            for (int j = 0; j < 4; j++)
                O[o + j] = oacc[i][j] * inv;
        }
    }
}

// ===========================================================================
// Output projection: out[b,t,j] = sum_i Oc[b,t,i] * Wo[j,i] + bo[j]
// Grid: (16 j-tiles, 16 t-tiles, 8 batch). Block 256. 64x64 tile, K-chunk 16.
// ===========================================================================
__global__ __launch_bounds__(256, 4)
void proj_kernel(const float* __restrict__ A, const float* __restrict__ Wo,
                 const float* __restrict__ bo, float* __restrict__ out)
{
    __shared__ float As[16][68];  // As[kk][t]
    __shared__ float Bs[16][68];  // Bs[kk][j]

    const int tid = threadIdx.x;
    const int ty = tid >> 4, tx = tid & 15;
    const int j0 = blockIdx.x * 64;
    const int t0 = blockIdx.y * 64;
    const int b  = blockIdx.z;

    float acc[4][4];
#pragma unroll
    for (int i = 0; i < 4; i++)
#pragma unroll
        for (int j = 0; j < 4; j++) acc[i][j] = 0.f;

    const float* Ab = A + (size_t)b * CDIM * POS;

    for (int i0 = 0; i0 < 1024; i0 += 16) {
        for (int idx = tid; idx < 1024; idx += 256) {
            int r = idx >> 4, kk = idx & 15;
            As[kk][r] = Ab[(size_t)(t0 + r) * 1024 + i0 + kk];
            Bs[kk][r] = Wo[(size_t)(j0 + r) * 1024 + i0 + kk];
        }
        __syncthreads();
#pragma unroll
        for (int kk = 0; kk < 16; kk++) {
            float4 a4 = *(const float4*)(&As[kk][ty * 4]);
            float4 w4 = *(const float4*)(&Bs[kk][tx * 4]);
            acc[0][0] += a4.x * w4.x; acc[0][1] += a4.x * w4.y;
            acc[0][2] += a4.x * w4.z; acc[0][3] += a4.x * w4.w;
            acc[1][0] += a4.y * w4.x; acc[1][1] += a4.y * w4.y;
            acc[1][2] += a4.y * w4.z; acc[1][3] += a4.y * w4.w;
            acc[2][0] += a4.z * w4.x; acc[2][1] += a4.z * w4.y;
            acc[2][2] += a4.z * w4.z; acc[2][3] += a4.z * w4.w;
            acc[3][0] += a4.w * w4.x; acc[3][1] += a4.w * w4.y;
            acc[3][2] += a4.w * w4.z; acc[3][3] += a4.w * w4.w;
        }
        __syncthreads();
    }

#pragma unroll
    for (int i = 0; i < 4; i++) {
        size_t o = ((size_t)b * CDIM + t0 + ty * 4 + i) * 1024 + j0 + tx * 4;
#pragma unroll
        for (int j = 0; j < 4; j++)
            out[o + j] = acc[i][j] + bo[j0 + tx * 4 + j];
    }
}

// ===========================================================================
extern "C" void kernel_launch(void* const* d_in, const int* in_sizes, int n_in,
                              void* d_out, int out_size)
{
    const float* q    = (const float*)d_in[0];
    const float* k    = (const float*)d_in[1];
    const float* v    = (const float*)d_in[2];
    const float* Wq   = (const float*)d_in[3];
    const float* bq   = (const float*)d_in[4];
    const float* Wk   = (const float*)d_in[5];
    const float* bk   = (const float*)d_in[6];
    const float* Wv   = (const float*)d_in[7];
    const float* bv   = (const float*)d_in[8];
    const float* Wo   = (const float*)d_in[9];
    const float* bo   = (const float*)d_in[10];
    const int*   mask = (const int*)d_in[11];
    float* out = (float*)d_out;

    float *Qc, *Kc, *Vc, *Oc;
    cudaGetSymbolAddress((void**)&Qc, g_Qc);
    cudaGetSymbolAddress((void**)&Kc, g_Kc);
    cudaGetSymbolAddress((void**)&Vc, g_Vc);
    cudaGetSymbolAddress((void**)&Oc, g_Oc);

    cudaFuncSetAttribute(attn_kernel, cudaFuncAttributeMaxDynamicSharedMemorySize,
                         ATTN_SMEM_BYTES);

    dim3 cgrid(16, 16, 8);
    conv3x3_kernel<<<cgrid, 256>>>(q, Wq, bq, Qc);
    conv3x3_kernel<<<cgrid, 256>>>(k, Wk, bk, Kc);
    conv3x3_kernel<<<cgrid, 256>>>(v, Wv, bv, Vc);

    dim3 agrid(16, 16, 8);
    attn_kernel<<<agrid, 256, ATTN_SMEM_BYTES>>>(Qc, Kc, Vc, mask, Oc);

    dim3 pgrid(16, 16, 8);
    proj_kernel<<<pgrid, 256>>>(Oc, Wo, bo, out);
}

// round 2
// speedup vs baseline: 1.4301x; 1.4301x over previous
#include <cuda_runtime.h>
#include <cstdint>

// ---------------------------------------------------------------------------
// MultiHeadAttn: conv3x3(q/k/v) -> 16-head attention over channels -> Wo proj
// B=8, C=1024 (tokens), HW=32x32 (features: 16 heads x 64), fp32 + FFMA2.
// ---------------------------------------------------------------------------

#define BATCH 8
#define CDIM  1024
#define POS   1024
#define NHEAD 16
#define HDIM  64

__device__ float g_Qc[BATCH * CDIM * POS];
__device__ float g_Kc[BATCH * CDIM * POS];
__device__ float g_Vc[BATCH * CDIM * POS];
__device__ float g_Oc[BATCH * CDIM * POS];

// ---- packed f32x2 helpers (sm_103a FFMA2 path) ----
__device__ __forceinline__ unsigned long long pack2(float lo, float hi) {
    unsigned long long r;
    asm("mov.b64 %0, {%1, %2};" : "=l"(r) : "f"(lo), "f"(hi));
    return r;
}
__device__ __forceinline__ unsigned long long fma2(unsigned long long a,
                                                   unsigned long long b,
                                                   unsigned long long c) {
    unsigned long long d;
    asm("fma.rn.f32x2 %0, %1, %2, %3;" : "=l"(d) : "l"(a), "l"(b), "l"(c));
    return d;
}
__device__ __forceinline__ unsigned long long mul2(unsigned long long a,
                                                   unsigned long long b) {
    unsigned long long d;
    asm("mul.rn.f32x2 %0, %1, %2;" : "=l"(d) : "l"(a), "l"(b));
    return d;
}
__device__ __forceinline__ float2 unpack2(unsigned long long v) {
    float2 f;
    asm("mov.b64 {%0, %1}, %2;" : "=f"(f.x), "=f"(f.y) : "l"(v));
    return f;
}

// ===========================================================================
// Conv3x3 (SAME, NCHW/OIHW) as implicit GEMM with FFMA2.
// Grid: (16 co-tiles, 16 row-pairs, 8 batch). Block 256, 2 blocks/SM.
// Tile: 64 co x 64 pos. Thread: 2 co-pairs x (2 rows x 2 cols) packed outputs.
// Register prefetch of next (x, W) stage overlaps LDG with math.
// ===========================================================================
#define CK 4
#define WSP 66   // padded co-stride for ws to break bank conflicts

__global__ __launch_bounds__(256, 2)
void conv3x3_kernel(const float* __restrict__ x, const float* __restrict__ W,
                    const float* __restrict__ bias, float* __restrict__ y)
{
    __shared__ __align__(16) float xs[CK][4][34];    // rows 2*by-1..+2, cols -1..32
    __shared__ __align__(16) float ws[CK * 9][WSP];  // [ck*9+k][co]

    const int tid = threadIdx.x;
    const int co0 = blockIdx.x * 64;
    const int by  = blockIdx.y;
    const int b   = blockIdx.z;
    const int ty = tid >> 4, tx = tid & 15;

    const float* xb = x + (size_t)b * CDIM * POS;

    // acc2[p][orow*2+oc]: lo = co0+ty*4+2p, hi = +1
    unsigned long long acc2[2][4];
#pragma unroll
    for (int p = 0; p < 2; p++)
#pragma unroll
        for (int j = 0; j < 4; j++) acc2[p][j] = 0ull;

    // ---- prefetch registers ----
    float xr_[3];  // 544 x-elements / 256 threads
    float wr_[9];  // 2304 w-elements / 256 threads

    auto fetchX = [&](int ci0, int idx) -> float {
        int ck = idx / 136, rem = idx - ck * 136;
        int lr = rem / 34,  lx  = rem - lr * 34;
        int gy = 2 * by + lr - 1, gx = lx - 1;
        if ((unsigned)gy < 32u && (unsigned)gx < 32u)
            return xb[(size_t)(ci0 + ck) * 1024 + gy * 32 + gx];
        return 0.f;
    };
    auto fetchW = [&](int ci0, int idx) -> float {
        // 36 consecutive floats per co: W[co][ci0..ci0+3][0..8]
        int co = idx / 36, q = idx - co * 36;
        return W[(size_t)(co0 + co) * 9216 + (size_t)ci0 * 9 + q];
    };

#pragma unroll
    for (int it = 0; it < 3; it++) {
        int idx = tid + 256 * it;
        xr_[it] = (idx < 544) ? fetchX(0, idx) : 0.f;
    }
#pragma unroll
    for (int it = 0; it < 9; it++)
        wr_[it] = fetchW(0, tid + 256 * it);

    for (int ci0 = 0; ci0 < CDIM; ci0 += CK) {
        // ---- commit prefetched stage to smem ----
#pragma unroll
        for (int it = 0; it < 3; it++) {
            int idx = tid + 256 * it;
            if (idx < 544) {
                int ck = idx / 136, rem = idx - ck * 136;
                int lr = rem / 34,  lx  = rem - lr * 34;
                xs[ck][lr][lx] = xr_[it];
            }
        }
#pragma unroll
        for (int it = 0; it < 9; it++) {
            int idx = tid + 256 * it;
            int co = idx / 36, q = idx - co * 36;   // q = ck*9 + k
            ws[q][co] = wr_[it];
        }
        __syncthreads();

        // ---- prefetch next stage (LDG in flight during math) ----
        if (ci0 + CK < CDIM) {
#pragma unroll
            for (int it = 0; it < 3; it++) {
                int idx = tid + 256 * it;
                xr_[it] = (idx < 544) ? fetchX(ci0 + CK, idx) : 0.f;
            }
#pragma unroll
            for (int it = 0; it < 9; it++)
                wr_[it] = fetchW(ci0 + CK, tid + 256 * it);
        }

        // ---- math ----
#pragma unroll
        for (int ck = 0; ck < CK; ck++) {
            unsigned long long xbb[4][4];  // broadcast packs (x,x)
#pragma unroll
            for (int lr = 0; lr < 4; lr++) {
                float2 a = *(const float2*)&xs[ck][lr][tx * 2];
                float2 c = *(const float2*)&xs[ck][lr][tx * 2 + 2];
                xbb[lr][0] = pack2(a.x, a.x);
                xbb[lr][1] = pack2(a.y, a.y);
                xbb[lr][2] = pack2(c.x, c.x);
                xbb[lr][3] = pack2(c.y, c.y);
            }
#pragma unroll
            for (int p = 0; p < 2; p++) {
                unsigned long long w2[9];
#pragma unroll
                for (int k = 0; k < 9; k++)
                    w2[k] = *(const unsigned long long*)&ws[ck * 9 + k][ty * 4 + p * 2];
#pragma unroll
                for (int orow = 0; orow < 2; orow++)
#pragma unroll
                    for (int oc = 0; oc < 2; oc++) {
                        unsigned long long a = acc2[p][orow * 2 + oc];
#pragma unroll
                        for (int ky = 0; ky < 3; ky++)
#pragma unroll
                            for (int kx = 0; kx < 3; kx++)
                                a = fma2(w2[ky * 3 + kx], xbb[orow + ky][oc + kx], a);
                        acc2[p][orow * 2 + oc] = a;
                    }
            }
        }
        __syncthreads();
    }

    // ---- epilogue ----
#pragma unroll
    for (int p = 0; p < 2; p++) {
        int co = co0 + ty * 4 + p * 2;
        float b0 = bias[co], b1 = bias[co + 1];
#pragma unroll
        for (int orow = 0; orow < 2; orow++)
#pragma unroll
            for (int oc = 0; oc < 2; oc++) {
                float2 v = unpack2(acc2[p][orow * 2 + oc]);
                int pos = (2 * by + orow) * 32 + tx * 2 + oc;
                y[((size_t)b * CDIM + co) * POS + pos]       = v.x + b0;
                y[((size_t)b * CDIM + co + 1) * POS + pos]   = v.y + b1;
            }
    }
}

// ===========================================================================
// Flash-style attention over channels (FFMA2 in both GEMM phases).
// Grid: (16 t-tiles, 16 heads, 8 batch). Block 256.
// ===========================================================================
#define SP 68
#define ATTN_SMEM_BYTES ((4 * 64 * SP + 3 * 64 + 64 * 4) * 4)

__global__ __launch_bounds__(256, 3)
void attn_kernel(const float* __restrict__ Q, const float* __restrict__ K,
                 const float* __restrict__ V, const int* __restrict__ mask,
                 float* __restrict__ O)
{
    extern __shared__ float sm[];
    float* Qs   = sm;                 // [64 d][SP]
    float* Ks   = Qs + 64 * SP;       // [64 d][SP]
    float* Vs   = Ks + 64 * SP;       // [64 s][SP]
    float* Ss   = Vs + 64 * SP;       // [64 s][SP]
    float* mrow = Ss + 64 * SP;
    float* lrow = mrow + 64;
    float* frow = lrow + 64;
    float* pbuf = frow + 64;

    const int tid = threadIdx.x;
    const int t0 = blockIdx.x * 64;
    const int h  = blockIdx.y;
    const int b  = blockIdx.z;
    const int ty = tid >> 4, tx = tid & 15;
    const int h64 = h * 64;
    const size_t base = (size_t)b * CDIM * POS;

    for (int idx = tid; idx < 4096; idx += 256) {
        int r = idx >> 6, d = idx & 63;
        Qs[d * SP + r] = Q[base + (size_t)(t0 + r) * 1024 + h64 + d] * 0.125f;
    }
    if (tid < 64) { mrow[tid] = -3.0e38f; lrow[tid] = 0.f; frow[tid] = 1.f; }

    unsigned long long o2[4][2];
#pragma unroll
    for (int i = 0; i < 4; i++) { o2[i][0] = 0ull; o2[i][1] = 0ull; }

    const int rr   = tid & 63;
    const int part = tid >> 6;

    for (int s0 = 0; s0 < 1024; s0 += 64) {
        __syncthreads();  // (A)
        for (int idx = tid; idx < 4096; idx += 256) {
            int s = idx >> 6, d = idx & 63;
            size_t g = base + (size_t)(s0 + s) * 1024 + h64 + d;
            Ks[d * SP + s] = K[g];
            Vs[s * SP + d] = V[g];
            int mm = mask[base + (size_t)(t0 + s) * 1024 + s0 + d];
            Ss[d * SP + s] = __int_as_float(mm);
        }
        __syncthreads();  // (B)

        // Phase A: S = Q Kt (rows tx*4.., cols ty*4..), FFMA2 over col pairs
        {
            const int ra = tx * 4, ca = ty * 4;
            unsigned long long s2[4][2];
#pragma unroll
            for (int i = 0; i < 4; i++) { s2[i][0] = 0ull; s2[i][1] = 0ull; }
#pragma unroll 8
            for (int d = 0; d < 64; d++) {
                float4 q4 = *(const float4*)(Qs + d * SP + ra);
                float4 k4 = *(const float4*)(Ks + d * SP + ca);
                unsigned long long k01 = pack2(k4.x, k4.y);
                unsigned long long k23 = pack2(k4.z, k4.w);
                unsigned long long qb;
                qb = pack2(q4.x, q4.x);
                s2[0][0] = fma2(qb, k01, s2[0][0]); s2[0][1] = fma2(qb, k23, s2[0][1]);
                qb = pack2(q4.y, q4.y);
                s2[1][0] = fma2(qb, k01, s2[1][0]); s2[1][1] = fma2(qb, k23, s2[1][1]);
                qb = pack2(q4.z, q4.z);
                s2[2][0] = fma2(qb, k01, s2[2][0]); s2[2][1] = fma2(qb, k23, s2[2][1]);
                qb = pack2(q4.w, q4.w);
                s2[3][0] = fma2(qb, k01, s2[3][0]); s2[3][1] = fma2(qb, k23, s2[3][1]);
            }
            float sacc[4][4];
#pragma unroll
            for (int i = 0; i < 4; i++) {
                float2 u = unpack2(s2[i][0]); sacc[i][0] = u.x; sacc[i][1] = u.y;
                float2 w = unpack2(s2[i][1]); sacc[i][2] = w.x; sacc[i][3] = w.y;
            }
#pragma unroll
            for (int j = 0; j < 4; j++) {
                float* cell = Ss + (ca + j) * SP + ra;
                float4 sv;
                sv.x = (__float_as_int(cell[0]) == 0) ? -1e9f : sacc[0][j];
                sv.y = (__float_as_int(cell[1]) == 0) ? -1e9f : sacc[1][j];
                sv.z = (__float_as_int(cell[2]) == 0) ? -1e9f : sacc[2][j];
                sv.w = (__float_as_int(cell[3]) == 0) ? -1e9f : sacc[3][j];
                *(float4*)cell = sv;
            }
        }
        __syncthreads();  // (C)

        // Phase B: online softmax
        {
            float pm = -3.0e38f;
#pragma unroll
            for (int j = 0; j < 16; j++)
                pm = fmaxf(pm, Ss[(part * 16 + j) * SP + rr]);
            pbuf[rr * 4 + part] = pm;
        }
        __syncthreads();  // (D)
        if (tid < 64) {
            float bm = fmaxf(fmaxf(pbuf[tid * 4 + 0], pbuf[tid * 4 + 1]),
                             fmaxf(pbuf[tid * 4 + 2], pbuf[tid * 4 + 3]));
            float mnew = fmaxf(mrow[tid], bm);
            frow[tid] = __expf(mrow[tid] - mnew);
            mrow[tid] = mnew;
        }
        __syncthreads();  // (E)
        {
            float mr = mrow[rr];
            float ps = 0.f;
#pragma unroll
            for (int j = 0; j < 16; j++) {
                int s = part * 16 + j;
                float p = __expf(Ss[s * SP + rr] - mr);
                Ss[s * SP + rr] = p;
                ps += p;
            }
            pbuf[rr * 4 + part] = ps;
        }
        __syncthreads();  // (F)
        if (tid < 64) {
            lrow[tid] = lrow[tid] * frow[tid] +
                        pbuf[tid * 4 + 0] + pbuf[tid * 4 + 1] +
                        pbuf[tid * 4 + 2] + pbuf[tid * 4 + 3];
        }
        // Rescale packed accumulators
        {
            const int r0 = ty * 4;
#pragma unroll
            for (int i = 0; i < 4; i++) {
                unsigned long long f2 = pack2(frow[r0 + i], frow[r0 + i]);
                o2[i][0] = mul2(o2[i][0], f2);
                o2[i][1] = mul2(o2[i][1], f2);
            }
        }
        __syncthreads();  // (G)

        // Phase C: O += P V (rows ty*4.., cols tx*4..), FFMA2 over col pairs
        {
            const int r0 = ty * 4, c0 = tx * 4;
#pragma unroll 8
            for (int s = 0; s < 64; s++) {
                float4 p4 = *(const float4*)(Ss + s * SP + r0);
                float4 v4 = *(const float4*)(Vs + s * SP + c0);
                unsigned long long v01 = pack2(v4.x, v4.y);
                unsigned long long v23 = pack2(v4.z, v4.w);
                unsigned long long pb;
                pb = pack2(p4.x, p4.x);
                o2[0][0] = fma2(pb, v01, o2[0][0]); o2[0][1] = fma2(pb, v23, o2[0][1]);
                pb = pack2(p4.y, p4.y);
                o2[1][0] = fma2(pb, v01, o2[1][0]); o2[1][1] = fma2(pb, v23, o2[1][1]);
                pb = pack2(p4.z, p4.z);
                o2[2][0] = fma2(pb, v01, o2[2][0]); o2[2][1] = fma2(pb, v23, o2[2][1]);
                pb = pack2(p4.w, p4.w);
                o2[3][0] = fma2(pb, v01, o2[3][0]); o2[3][1] = fma2(pb, v23, o2[3][1]);
            }
        }
    }
    __syncthreads();

    {
        const int r0 = ty * 4, c0 = tx * 4;
#pragma unroll
        for (int i = 0; i < 4; i++) {
            float inv = 1.0f / lrow[r0 + i];
            size_t o = base + (size_t)(t0 + r0 + i) * 1024 + h64 + c0;
            float2 u = unpack2(o2[i][0]);
            float2 w = unpack2(o2[i][1]);
            O[o + 0] = u.x * inv;
            O[o + 1] = u.y * inv;
            O[o + 2] = w.x * inv;
            O[o + 3] = w.y * inv;
        }
    }
}

// ===========================================================================
// Output projection with FFMA2: out[b,t,j] = sum_i Oc[b,t,i]*Wo[j,i] + bo[j]
// ===========================================================================
__global__ __launch_bounds__(256, 4)
void proj_kernel(const float* __restrict__ A, const float* __restrict__ Wo,
                 const float* __restrict__ bo, float* __restrict__ out)
{
    __shared__ float As[16][68];
    __shared__ float Bs[16][68];

    const int tid = threadIdx.x;
    const int ty = tid >> 4, tx = tid & 15;
    const int j0 = blockIdx.x * 64;
    const int t0 = blockIdx.y * 64;
    const int b  = blockIdx.z;

    unsigned long long acc2[4][2];
#pragma unroll
    for (int i = 0; i < 4; i++) { acc2[i][0] = 0ull; acc2[i][1] = 0ull; }

    const float* Ab = A + (size_t)b * CDIM * POS;

    for (int i0 = 0; i0 < 1024; i0 += 16) {
        for (int idx = tid; idx < 1024; idx += 256) {
            int r = idx >> 4, kk = idx & 15;
            As[kk][r] = Ab[(size_t)(t0 + r) * 1024 + i0 + kk];
            Bs[kk][r] = Wo[(size_t)(j0 + r) * 1024 + i0 + kk];
        }
        __syncthreads();
#pragma unroll
        for (int kk = 0; kk < 16; kk++) {
            float4 a4 = *(const float4*)(&As[kk][ty * 4]);
            float4 w4 = *(const float4*)(&Bs[kk][tx * 4]);
            unsigned long long w01 = pack2(w4.x, w4.y);
            unsigned long long w23 = pack2(w4.z, w4.w);
            unsigned long long ab;
            ab = pack2(a4.x, a4.x);
            acc2[0][0] = fma2(ab, w01, acc2[0][0]); acc2[0][1] = fma2(ab, w23, acc2[0][1]);
            ab = pack2(a4.y, a4.y);
            acc2[1][0] = fma2(ab, w01, acc2[1][0]); acc2[1][1] = fma2(ab, w23, acc2[1][1]);
            ab = pack2(a4.z, a4.z);
            acc2[2][0] = fma2(ab, w01, acc2[2][0]); acc2[2][1] = fma2(ab, w23, acc2[2][1]);
            ab = pack2(a4.w, a4.w);
            acc2[3][0] = fma2(ab, w01, acc2[3][0]); acc2[3][1] = fma2(ab, w23, acc2[3][1]);
        }
        __syncthreads();
    }

#pragma unroll
    for (int i = 0; i < 4; i++) {
        size_t o = ((size_t)b * CDIM + t0 + ty * 4 + i) * 1024 + j0 + tx * 4;
        float2 u = unpack2(acc2[i][0]);
        float2 w = unpack2(acc2[i][1]);
        out[o + 0] = u.x + bo[j0 + tx * 4 + 0];
        out[o + 1] = u.y + bo[j0 + tx * 4 + 1];
        out[o + 2] = w.x + bo[j0 + tx * 4 + 2];
        out[o + 3] = w.y + bo[j0 + tx * 4 + 3];
    }
}

// ===========================================================================
extern "C" void kernel_launch(void* const* d_in, const int* in_sizes, int n_in,
                              void* d_out, int out_size)
{
    const float* q    = (const float*)d_in[0];
    const float* k    = (const float*)d_in[1];
    const float* v    = (const float*)d_in[2];
    const float* Wq   = (const float*)d_in[3];
    const float* bq   = (const float*)d_in[4];
    const float* Wk   = (const float*)d_in[5];
    const float* bk   = (const float*)d_in[6];
    const float* Wv   = (const float*)d_in[7];
    const float* bv   = (const float*)d_in[8];
    const float* Wo   = (const float*)d_in[9];
    const float* bo   = (const float*)d_in[10];
    const int*   mask = (const int*)d_in[11];
    float* out = (float*)d_out;

    float *Qc, *Kc, *Vc, *Oc;
    cudaGetSymbolAddress((void**)&Qc, g_Qc);
    cudaGetSymbolAddress((void**)&Kc, g_Kc);
    cudaGetSymbolAddress((void**)&Vc, g_Vc);
    cudaGetSymbolAddress((void**)&Oc, g_Oc);

    cudaFuncSetAttribute(attn_kernel, cudaFuncAttributeMaxDynamicSharedMemorySize,
                         ATTN_SMEM_BYTES);

    dim3 cgrid(16, 16, 8);
    conv3x3_kernel<<<cgrid, 256>>>(q, Wq, bq, Qc);
    conv3x3_kernel<<<cgrid, 256>>>(k, Wk, bk, Kc);
    conv3x3_kernel<<<cgrid, 256>>>(v, Wv, bv, Vc);

    dim3 agrid(16, 16, 8);
    attn_kernel<<<agrid, 256, ATTN_SMEM_BYTES>>>(Qc, Kc, Vc, mask, Oc);

    dim3 pgrid(16, 16, 8);
    proj_kernel<<<pgrid, 256>>>(Oc, Wo, bo, out);
}

// round 4
// speedup vs baseline: 2.7918x; 1.9522x over previous
#include <cuda_runtime.h>
#include <cuda_bf16.h>
#include <cstdint>

// ---------------------------------------------------------------------------
// MultiHeadAttn: conv3x3(q/k/v) via mma.sync bf16x3-split implicit GEMM
//                -> 16-head attention over channels (FFMA2) -> Wo proj (FFMA2)
// B=8, C=1024 tokens, 32x32 spatial (16 heads x 64).
// NOTE: tcgen05 is NOT available (harness PTX target is compute_103, no 'a').
// ---------------------------------------------------------------------------

#define BATCH 8
#define CDIM  1024
#define POS   1024

__device__ float g_Qc[BATCH * CDIM * POS];
__device__ float g_Kc[BATCH * CDIM * POS];
__device__ float g_Vc[BATCH * CDIM * POS];
__device__ float g_Oc[BATCH * CDIM * POS];

__device__ __nv_bfloat16 g_xt_hi[BATCH * POS * CDIM];
__device__ __nv_bfloat16 g_xt_lo[BATCH * POS * CDIM];
__device__ __nv_bfloat16 g_wt_hi[9 * CDIM * CDIM];
__device__ __nv_bfloat16 g_wt_lo[9 * CDIM * CDIM];

// ======================= helpers =============================
__device__ __forceinline__ uint32_t smem_to_u32(const void* p) {
    uint32_t a;
    asm("{ .reg .u64 t; cvta.to.shared.u64 t, %1; cvt.u32.u64 %0, t; }"
        : "=r"(a) : "l"(p));
    return a;
}
#define SMEM_SWIZZLE_128B(off) ((off) ^ (((off) >> 3) & 0x70))

#define CP16(dst, src, vsz) \
    asm volatile("cp.async.cg.shared.global [%0], [%1], 16, %2;" \
                 :: "r"((uint32_t)(dst)), "l"(src), "r"(vsz))
#define CP_COMMIT() asm volatile("cp.async.commit_group;" ::: "memory")
#define CP_WAIT(n)  asm volatile("cp.async.wait_group %0;" :: "n"(n) : "memory")

__device__ __forceinline__ void ldx4(uint32_t* r, uint32_t addr) {
    asm volatile("ldmatrix.sync.aligned.m8n8.x4.shared.b16 {%0,%1,%2,%3}, [%4];"
                 : "=r"(r[0]), "=r"(r[1]), "=r"(r[2]), "=r"(r[3]) : "r"(addr));
}
__device__ __forceinline__ void mma16816(float* d, const uint32_t* a,
                                         uint32_t b0, uint32_t b1) {
    asm volatile(
        "mma.sync.aligned.m16n8k16.row.col.f32.bf16.bf16.f32 "
        "{%0,%1,%2,%3}, {%4,%5,%6,%7}, {%8,%9}, {%0,%1,%2,%3};"
        : "+f"(d[0]), "+f"(d[1]), "+f"(d[2]), "+f"(d[3])
        : "r"(a[0]), "r"(a[1]), "r"(a[2]), "r"(a[3]), "r"(b0), "r"(b1));
}

// ---- packed f32x2 helpers (FFMA2) ----
__device__ __forceinline__ unsigned long long pack2(float lo, float hi) {
    unsigned long long r;
    asm("mov.b64 %0, {%1, %2};" : "=l"(r) : "f"(lo), "f"(hi));
    return r;
}
__device__ __forceinline__ unsigned long long fma2(unsigned long long a,
                                                   unsigned long long b,
                                                   unsigned long long c) {
    unsigned long long d;
    asm("fma.rn.f32x2 %0, %1, %2, %3;" : "=l"(d) : "l"(a), "l"(b), "l"(c));
    return d;
}
__device__ __forceinline__ unsigned long long mul2(unsigned long long a,
                                                   unsigned long long b) {
    unsigned long long d;
    asm("mul.rn.f32x2 %0, %1, %2;" : "=l"(d) : "l"(a), "l"(b));
    return d;
}
__device__ __forceinline__ float2 unpack2(unsigned long long v) {
    float2 f;
    asm("mov.b64 {%0, %1}, %2;" : "=f"(f.x), "=f"(f.y) : "l"(v));
    return f;
}

// ===========================================================================
// convert_W: W[co][ci][k] fp32 -> Wt[k][co][ci] bf16 hi/lo. Grid 1024, blk 256.
// ===========================================================================
__global__ __launch_bounds__(256)
void convert_W_kernel(const float* __restrict__ W,
                      __nv_bfloat16* __restrict__ wh, __nv_bfloat16* __restrict__ wl)
{
    __shared__ float ws[9216];
    const int tid = threadIdx.x;
    const int co = blockIdx.x;
    for (int i = tid; i < 9216; i += 256) ws[i] = W[(size_t)co * 9216 + i];
    __syncthreads();
#pragma unroll
    for (int k = 0; k < 9; k++)
        for (int ci = tid; ci < 1024; ci += 256) {
            float f = ws[ci * 9 + k];
            __nv_bfloat16 hi = __float2bfloat16(f);
            float lof = f - __bfloat162float(hi);
            size_t o = ((size_t)k * 1024 + co) * 1024 + ci;
            wh[o] = hi;
            wl[o] = __float2bfloat16(lof);
        }
}

// ===========================================================================
// convert_x: x[b][ci][p] fp32 -> xt[b][p][ci] bf16 hi/lo (transpose + split).
// ===========================================================================
__global__ __launch_bounds__(256)
void convert_x_kernel(const float* __restrict__ x,
                      __nv_bfloat16* __restrict__ xh, __nv_bfloat16* __restrict__ xl)
{
    __shared__ float ts[32][33];
    const int b = blockIdx.z, ci0 = blockIdx.x * 32, p0 = blockIdx.y * 32;
    const int tx = threadIdx.x, ty = threadIdx.y;
#pragma unroll
    for (int r = 0; r < 4; r++)
        ts[ty + 8 * r][tx] = x[((size_t)b * 1024 + ci0 + ty + 8 * r) * 1024 + p0 + tx];
    __syncthreads();
#pragma unroll
    for (int r = 0; r < 4; r++) {
        int pl = ty + 8 * r;
        float f = ts[tx][pl];
        __nv_bfloat16 hi = __float2bfloat16(f);
        float lof = f - __bfloat162float(hi);
        size_t o = ((size_t)b * 1024 + p0 + pl) * 1024 + ci0 + tx;
        xh[o] = hi;
        xl[o] = __float2bfloat16(lof);
    }
}

// ===========================================================================
// conv_mma: mma.sync implicit-GEMM 3x3 conv, bf16x3 split, fp32 accum.
// Grid (8 co-tiles, 8 pos-tiles, 8 batch). Block 256 (8 warps), 1 CTA/SM.
// CTA tile: 128co x 128pos. 144 stages (9 taps x 16 ci-chunks of 64).
// Stage smem: Ah 16K | Al 16K | Bh 16K | Bl 16K = 64K; double buffered.
// Warp tile: 64co x 32pos (warps 2x4).
// ===========================================================================
#define NSTAGE 144
#define STG    65536
#define CONV_SMEM (2 * STG)

__global__ __launch_bounds__(256, 1)
void conv_mma_kernel(const __nv_bfloat16* __restrict__ Ah,
                     const __nv_bfloat16* __restrict__ Al,
                     const __nv_bfloat16* __restrict__ Bh,
                     const __nv_bfloat16* __restrict__ Bl,
                     const float* __restrict__ bias, float* __restrict__ y)
{
    extern __shared__ __align__(1024) char smc[];
    const uint32_t sb = smem_to_u32(smc);
    const int tid = threadIdx.x;
    const int wid = tid >> 5, lane = tid & 31;
    const int co0  = blockIdx.x * 128;
    const int pos0 = blockIdx.y * 128;
    const int b    = blockIdx.z;
    const int co_w  = (wid & 1) * 64;
    const int pos_w = (wid >> 1) * 32;

    float acc[4][4][4];
#pragma unroll
    for (int i = 0; i < 4; i++)
#pragma unroll
        for (int j = 0; j < 4; j++)
#pragma unroll
            for (int k = 0; k < 4; k++) acc[i][j][k] = 0.f;

    auto load_stage = [&](int s) {
        const int buf = s & 1;
        const int tap = s >> 4, chunk = s & 15;
        const int ci0 = chunk * 64;
        const int dy = tap / 3 - 1, dx = tap % 3 - 1;
        const int shift = dy * 32 + dx;
        const uint32_t dbase = sb + buf * STG;

        const __nv_bfloat16* ah = Ah + ((size_t)tap * 1024 + co0) * 1024 + ci0;
        const __nv_bfloat16* al = Al + ((size_t)tap * 1024 + co0) * 1024 + ci0;
#pragma unroll
        for (int it = 0; it < 4; it++) {
            int idx = tid + it * 256;          // 0..1023
            int r = idx >> 3, seg = idx & 7;
            uint32_t d = SMEM_SWIZZLE_128B(r * 128 + seg * 16);
            CP16(dbase + d,         ah + (size_t)r * 1024 + seg * 8, 16);
            CP16(dbase + 16384 + d, al + (size_t)r * 1024 + seg * 8, 16);
        }
        const __nv_bfloat16* bh = Bh + (size_t)b * 1048576 + ci0;
        const __nv_bfloat16* bl = Bl + (size_t)b * 1048576 + ci0;
#pragma unroll
        for (int it = 0; it < 4; it++) {
            int idx = tid + it * 256;          // 0..1023
            int r = idx >> 3, seg = idx & 7;
            int p = pos0 + r;
            int ri = (p >> 5) + dy, cj = (p & 31) + dx;
            bool ok = ((unsigned)ri < 32u) && ((unsigned)cj < 32u);
            int vs = ok ? 16 : 0;
            size_t off = ok ? ((size_t)(p + shift) * 1024 + seg * 8) : 0;
            uint32_t d = SMEM_SWIZZLE_128B(r * 128 + seg * 16);
            CP16(dbase + 32768 + d, bh + off, vs);
            CP16(dbase + 49152 + d, bl + off, vs);
        }
    };

    load_stage(0);
    CP_COMMIT();

    const int lr = lane & 15, lk = lane >> 4;

    for (int s = 0; s < NSTAGE; s++) {
        if (s + 1 < NSTAGE) { load_stage(s + 1); CP_COMMIT(); CP_WAIT(1); }
        else                { CP_WAIT(0); }
        __syncthreads();

        const uint32_t bufb = sb + (s & 1) * STG;
#pragma unroll
        for (int ks = 0; ks < 4; ks++) {
            const uint32_t colb = ks * 32 + lk * 16;
            uint32_t a[4][4], bb[2][4];

            // --- A hi, B hi: hh term ---
#pragma unroll
            for (int mt = 0; mt < 4; mt++)
                ldx4(a[mt], bufb + SMEM_SWIZZLE_128B((co_w + mt * 16 + lr) * 128 + colb));
#pragma unroll
            for (int nt = 0; nt < 2; nt++)
                ldx4(bb[nt], bufb + 32768 + SMEM_SWIZZLE_128B((pos_w + nt * 16 + lr) * 128 + colb));
#pragma unroll
            for (int mt = 0; mt < 4; mt++)
#pragma unroll
                for (int nt = 0; nt < 2; nt++) {
                    mma16816(acc[mt][nt * 2],     a[mt], bb[nt][0], bb[nt][2]);
                    mma16816(acc[mt][nt * 2 + 1], a[mt], bb[nt][1], bb[nt][3]);
                }

            // --- A hi, B lo: hl term ---
#pragma unroll
            for (int nt = 0; nt < 2; nt++)
                ldx4(bb[nt], bufb + 49152 + SMEM_SWIZZLE_128B((pos_w + nt * 16 + lr) * 128 + colb));
#pragma unroll
            for (int mt = 0; mt < 4; mt++)
#pragma unroll
                for (int nt = 0; nt < 2; nt++) {
                    mma16816(acc[mt][nt * 2],     a[mt], bb[nt][0], bb[nt][2]);
                    mma16816(acc[mt][nt * 2 + 1], a[mt], bb[nt][1], bb[nt][3]);
                }

            // --- A lo, B hi: lh term ---
#pragma unroll
            for (int mt = 0; mt < 4; mt++)
                ldx4(a[mt], bufb + 16384 + SMEM_SWIZZLE_128B((co_w + mt * 16 + lr) * 128 + colb));
#pragma unroll
            for (int nt = 0; nt < 2; nt++)
                ldx4(bb[nt], bufb + 32768 + SMEM_SWIZZLE_128B((pos_w + nt * 16 + lr) * 128 + colb));
#pragma unroll
            for (int mt = 0; mt < 4; mt++)
#pragma unroll
                for (int nt = 0; nt < 2; nt++) {
                    mma16816(acc[mt][nt * 2],     a[mt], bb[nt][0], bb[nt][2]);
                    mma16816(acc[mt][nt * 2 + 1], a[mt], bb[nt][1], bb[nt][3]);
                }
        }
        __syncthreads();
    }

    // ---- epilogue: C[co][pos] + bias -> y ----
    const int lq = lane >> 2, lrm = lane & 3;
#pragma unroll
    for (int mt = 0; mt < 4; mt++) {
        int r0 = co0 + co_w + mt * 16 + lq;
        float bv0 = bias[r0], bv1 = bias[r0 + 8];
        size_t row0 = ((size_t)b * 1024 + r0) * 1024 + pos0 + pos_w;
        size_t row1 = row0 + (size_t)8 * 1024;
#pragma unroll
        for (int j = 0; j < 4; j++) {
            int pofs = j * 8 + lrm * 2;
            *(float2*)(y + row0 + pofs) =
                make_float2(acc[mt][j][0] + bv0, acc[mt][j][1] + bv0);
            *(float2*)(y + row1 + pofs) =
                make_float2(acc[mt][j][2] + bv1, acc[mt][j][3] + bv1);
        }
    }
}

// ===========================================================================
// Flash-style attention over channels (FFMA2). Grid (16,16,8), block 256.
// ===========================================================================
#define SP 68
#define ATTN_SMEM_BYTES ((4 * 64 * SP + 3 * 64 + 64 * 4) * 4)

__global__ __launch_bounds__(256, 3)
void attn_kernel(const float* __restrict__ Q, const float* __restrict__ K,
                 const float* __restrict__ V, const int* __restrict__ mask,
                 float* __restrict__ O)
{
    extern __shared__ float smf[];
    float* Qs   = smf;
    float* Ks   = Qs + 64 * SP;
    float* Vs   = Ks + 64 * SP;
    float* Ss   = Vs + 64 * SP;
    float* mrow = Ss + 64 * SP;
    float* lrow = mrow + 64;
    float* frow = lrow + 64;
    float* pbuf = frow + 64;

    const int tid = threadIdx.x;
    const int t0 = blockIdx.x * 64;
    const int h  = blockIdx.y;
    const int b  = blockIdx.z;
    const int ty = tid >> 4, tx = tid & 15;
    const int h64 = h * 64;
    const size_t base = (size_t)b * CDIM * POS;

    for (int idx = tid; idx < 4096; idx += 256) {
        int r = idx >> 6, d = idx & 63;
        Qs[d * SP + r] = Q[base + (size_t)(t0 + r) * 1024 + h64 + d] * 0.125f;
    }
    if (tid < 64) { mrow[tid] = -3.0e38f; lrow[tid] = 0.f; frow[tid] = 1.f; }

    unsigned long long o2[4][2];
#pragma unroll
    for (int i = 0; i < 4; i++) { o2[i][0] = 0ull; o2[i][1] = 0ull; }

    const int rr   = tid & 63;
    const int part = tid >> 6;

    for (int s0 = 0; s0 < 1024; s0 += 64) {
        __syncthreads();
        for (int idx = tid; idx < 4096; idx += 256) {
            int s = idx >> 6, d = idx & 63;
            size_t g = base + (size_t)(s0 + s) * 1024 + h64 + d;
            Ks[d * SP + s] = K[g];
            Vs[s * SP + d] = V[g];
            int mm = mask[base + (size_t)(t0 + s) * 1024 + s0 + d];
            Ss[d * SP + s] = __int_as_float(mm);
        }
        __syncthreads();

        {
            const int ra = tx * 4, ca = ty * 4;
            unsigned long long s2[4][2];
#pragma unroll
            for (int i = 0; i < 4; i++) { s2[i][0] = 0ull; s2[i][1] = 0ull; }
#pragma unroll 8
            for (int d = 0; d < 64; d++) {
                float4 q4 = *(const float4*)(Qs + d * SP + ra);
                float4 k4 = *(const float4*)(Ks + d * SP + ca);
                unsigned long long k01 = pack2(k4.x, k4.y);
                unsigned long long k23 = pack2(k4.z, k4.w);
                unsigned long long qb;
                qb = pack2(q4.x, q4.x);
                s2[0][0] = fma2(qb, k01, s2[0][0]); s2[0][1] = fma2(qb, k23, s2[0][1]);
                qb = pack2(q4.y, q4.y);
                s2[1][0] = fma2(qb, k01, s2[1][0]); s2[1][1] = fma2(qb, k23, s2[1][1]);
                qb = pack2(q4.z, q4.z);
                s2[2][0] = fma2(qb, k01, s2[2][0]); s2[2][1] = fma2(qb, k23, s2[2][1]);
                qb = pack2(q4.w, q4.w);
                s2[3][0] = fma2(qb, k01, s2[3][0]); s2[3][1] = fma2(qb, k23, s2[3][1]);
            }
            float sacc[4][4];
#pragma unroll
            for (int i = 0; i < 4; i++) {
                float2 u = unpack2(s2[i][0]); sacc[i][0] = u.x; sacc[i][1] = u.y;
                float2 w = unpack2(s2[i][1]); sacc[i][2] = w.x; sacc[i][3] = w.y;
            }
#pragma unroll
            for (int j = 0; j < 4; j++) {
                float* cell = Ss + (ca + j) * SP + ra;
                float4 sv;
                sv.x = (__float_as_int(cell[0]) == 0) ? -1e9f : sacc[0][j];
                sv.y = (__float_as_int(cell[1]) == 0) ? -1e9f : sacc[1][j];
                sv.z = (__float_as_int(cell[2]) == 0) ? -1e9f : sacc[2][j];
                sv.w = (__float_as_int(cell[3]) == 0) ? -1e9f : sacc[3][j];
                *(float4*)cell = sv;
            }
        }
        __syncthreads();

        {
            float pm = -3.0e38f;
#pragma unroll
            for (int j = 0; j < 16; j++)
                pm = fmaxf(pm, Ss[(part * 16 + j) * SP + rr]);
            pbuf[rr * 4 + part] = pm;
        }
        __syncthreads();
        if (tid < 64) {
            float bm = fmaxf(fmaxf(pbuf[tid * 4 + 0], pbuf[tid * 4 + 1]),
                             fmaxf(pbuf[tid * 4 + 2], pbuf[tid * 4 + 3]));
            float mnew = fmaxf(mrow[tid], bm);
            frow[tid] = __expf(mrow[tid] - mnew);
            mrow[tid] = mnew;
        }
        __syncthreads();
        {
            float mr = mrow[rr];
            float ps = 0.f;
#pragma unroll
            for (int j = 0; j < 16; j++) {
                int s = part * 16 + j;
                float p = __expf(Ss[s * SP + rr] - mr);
                Ss[s * SP + rr] = p;
                ps += p;
            }
            pbuf[rr * 4 + part] = ps;
        }
        __syncthreads();
        if (tid < 64) {
            lrow[tid] = lrow[tid] * frow[tid] +
                        pbuf[tid * 4 + 0] + pbuf[tid * 4 + 1] +
                        pbuf[tid * 4 + 2] + pbuf[tid * 4 + 3];
        }
        {
            const int r0 = ty * 4;
#pragma unroll
            for (int i = 0; i < 4; i++) {
                unsigned long long f2 = pack2(frow[r0 + i], frow[r0 + i]);
                o2[i][0] = mul2(o2[i][0], f2);
                o2[i][1] = mul2(o2[i][1], f2);
            }
        }
        __syncthreads();

        {
            const int r0 = ty * 4, c0 = tx * 4;
#pragma unroll 8
            for (int s = 0; s < 64; s++) {
                float4 p4 = *(const float4*)(Ss + s * SP + r0);
                float4 v4 = *(const float4*)(Vs + s * SP + c0);
                unsigned long long v01 = pack2(v4.x, v4.y);
                unsigned long long v23 = pack2(v4.z, v4.w);
                unsigned long long pb;
                pb = pack2(p4.x, p4.x);
                o2[0][0] = fma2(pb, v01, o2[0][0]); o2[0][1] = fma2(pb, v23, o2[0][1]);
                pb = pack2(p4.y, p4.y);
                o2[1][0] = fma2(pb, v01, o2[1][0]); o2[1][1] = fma2(pb, v23, o2[1][1]);
                pb = pack2(p4.z, p4.z);
                o2[2][0] = fma2(pb, v01, o2[2][0]); o2[2][1] = fma2(pb, v23, o2[2][1]);
                pb = pack2(p4.w, p4.w);
                o2[3][0] = fma2(pb, v01, o2[3][0]); o2[3][1] = fma2(pb, v23, o2[3][1]);
            }
        }
    }
    __syncthreads();

    {
        const int r0 = ty * 4, c0 = tx * 4;
#pragma unroll
        for (int i = 0; i < 4; i++) {
            float inv = 1.0f / lrow[r0 + i];
            size_t o = base + (size_t)(t0 + r0 + i) * 1024 + h64 + c0;
            float2 u = unpack2(o2[i][0]);
            float2 w = unpack2(o2[i][1]);
            O[o + 0] = u.x * inv;
            O[o + 1] = u.y * inv;
            O[o + 2] = w.x * inv;
            O[o + 3] = w.y * inv;
        }
    }
}

// ===========================================================================
// Output projection (FFMA2)
// ===========================================================================
__global__ __launch_bounds__(256, 4)
void proj_kernel(const float* __restrict__ A, const float* __restrict__ Wo,
                 const float* __restrict__ bo, float* __restrict__ out)
{
    __shared__ float As[16][68];
    __shared__ float Bs[16][68];

    const int tid = threadIdx.x;
    const int ty = tid >> 4, tx = tid & 15;
    const int j0 = blockIdx.x * 64;
    const int t0 = blockIdx.y * 64;
    const int b  = blockIdx.z;

    unsigned long long acc2[4][2];
#pragma unroll
    for (int i = 0; i < 4; i++) { acc2[i][0] = 0ull; acc2[i][1] = 0ull; }

    const float* Ab = A + (size_t)b * CDIM * POS;

    for (int i0 = 0; i0 < 1024; i0 += 16) {
        for (int idx = tid; idx < 1024; idx += 256) {
            int r = idx >> 4, kk = idx & 15;
            As[kk][r] = Ab[(size_t)(t0 + r) * 1024 + i0 + kk];
            Bs[kk][r] = Wo[(size_t)(j0 + r) * 1024 + i0 + kk];
        }
        __syncthreads();
#pragma unroll
        for (int kk = 0; kk < 16; kk++) {
            float4 a4 = *(const float4*)(&As[kk][ty * 4]);
            float4 w4 = *(const float4*)(&Bs[kk][tx * 4]);
            unsigned long long w01 = pack2(w4.x, w4.y);
            unsigned long long w23 = pack2(w4.z, w4.w);
            unsigned long long ab;
            ab = pack2(a4.x, a4.x);
            acc2[0][0] = fma2(ab, w01, acc2[0][0]); acc2[0][1] = fma2(ab, w23, acc2[0][1]);
            ab = pack2(a4.y, a4.y);
            acc2[1][0] = fma2(ab, w01, acc2[1][0]); acc2[1][1] = fma2(ab, w23, acc2[1][1]);
            ab = pack2(a4.z, a4.z);
            acc2[2][0] = fma2(ab, w01, acc2[2][0]); acc2[2][1] = fma2(ab, w23, acc2[2][1]);
            ab = pack2(a4.w, a4.w);
            acc2[3][0] = fma2(ab, w01, acc2[3][0]); acc2[3][1] = fma2(ab, w23, acc2[3][1]);
        }
        __syncthreads();
    }

#pragma unroll
    for (int i = 0; i < 4; i++) {
        size_t o = ((size_t)b * CDIM + t0 + ty * 4 + i) * 1024 + j0 + tx * 4;
        float2 u = unpack2(acc2[i][0]);
        float2 w = unpack2(acc2[i][1]);
        out[o + 0] = u.x + bo[j0 + tx * 4 + 0];
        out[o + 1] = u.y + bo[j0 + tx * 4 + 1];
        out[o + 2] = w.x + bo[j0 + tx * 4 + 2];
        out[o + 3] = w.y + bo[j0 + tx * 4 + 3];
    }
}

// ===========================================================================
extern "C" void kernel_launch(void* const* d_in, const int* in_sizes, int n_in,
                              void* d_out, int out_size)
{
    const float* q    = (const float*)d_in[0];
    const float* k    = (const float*)d_in[1];
    const float* v    = (const float*)d_in[2];
    const float* Wq   = (const float*)d_in[3];
    const float* bq   = (const float*)d_in[4];
    const float* Wk   = (const float*)d_in[5];
    const float* bk   = (const float*)d_in[6];
    const float* Wv   = (const float*)d_in[7];
    const float* bv   = (const float*)d_in[8];
    const float* Wo   = (const float*)d_in[9];
    const float* bo   = (const float*)d_in[10];
    const int*   mask = (const int*)d_in[11];
    float* out = (float*)d_out;

    float *Qc, *Kc, *Vc, *Oc;
    cudaGetSymbolAddress((void**)&Qc, g_Qc);
    cudaGetSymbolAddress((void**)&Kc, g_Kc);
    cudaGetSymbolAddress((void**)&Vc, g_Vc);
    cudaGetSymbolAddress((void**)&Oc, g_Oc);
    __nv_bfloat16 *xh, *xl, *wh, *wl;
    cudaGetSymbolAddress((void**)&xh, g_xt_hi);
    cudaGetSymbolAddress((void**)&xl, g_xt_lo);
    cudaGetSymbolAddress((void**)&wh, g_wt_hi);
    cudaGetSymbolAddress((void**)&wl, g_wt_lo);

    cudaFuncSetAttribute(attn_kernel, cudaFuncAttributeMaxDynamicSharedMemorySize,
                         ATTN_SMEM_BYTES);
    cudaFuncSetAttribute(conv_mma_kernel, cudaFuncAttributeMaxDynamicSharedMemorySize,
                         CONV_SMEM);

    const float* xin[3] = {q, k, v};
    const float* Win[3] = {Wq, Wk, Wv};
    const float* bin[3] = {bq, bk, bv};
    float* yout[3] = {Qc, Kc, Vc};

    dim3 cxg(32, 32, 8), cxb(32, 8);
    dim3 mg(8, 8, 8);
    for (int i = 0; i < 3; i++) {
        convert_W_kernel<<<1024, 256>>>(Win[i], wh, wl);
        convert_x_kernel<<<cxg, cxb>>>(xin[i], xh, xl);
        conv_mma_kernel<<<mg, 256, CONV_SMEM>>>(wh, wl, xh, xl, bin[i], yout[i]);
    }

    dim3 agrid(16, 16, 8);
    attn_kernel<<<agrid, 256, ATTN_SMEM_BYTES>>>(Qc, Kc, Vc, mask, Oc);

    dim3 pgrid(16, 16, 8);
    proj_kernel<<<pgrid, 256>>>(Oc, Wo, bo, out);
}

// round 5
// speedup vs baseline: 3.1211x; 1.1179x over previous
#include <cuda_runtime.h>
#include <cuda_bf16.h>
#include <cstdint>

// ---------------------------------------------------------------------------
// MultiHeadAttn: conv3x3(q/k/v) via mma.sync bf16x3-split implicit GEMM
//  -> mma.sync flash attention (bf16x3 QK, P hi/lo PV) -> Wo proj (FFMA2)
// B=8, C=1024 tokens, 32x32 spatial (16 heads x 64). tcgen05 unavailable
// (harness targets compute_103 without 'a'), so warp-level mma.sync.
// ---------------------------------------------------------------------------

#define BATCH 8
#define CDIM  1024
#define POS   1024

__device__ float g_Oc[BATCH * CDIM * POS];

// conv outputs as bf16 hi/lo (Q prescaled by 0.125)
__device__ __nv_bfloat16 g_qh[BATCH * CDIM * POS];
__device__ __nv_bfloat16 g_ql[BATCH * CDIM * POS];
__device__ __nv_bfloat16 g_kh[BATCH * CDIM * POS];
__device__ __nv_bfloat16 g_kl[BATCH * CDIM * POS];
__device__ __nv_bfloat16 g_vh[BATCH * CDIM * POS];
__device__ __nv_bfloat16 g_vl[BATCH * CDIM * POS];

// conv input scratch
__device__ __nv_bfloat16 g_xt_hi[BATCH * POS * CDIM];
__device__ __nv_bfloat16 g_xt_lo[BATCH * POS * CDIM];
__device__ __nv_bfloat16 g_wt_hi[9 * CDIM * CDIM];
__device__ __nv_bfloat16 g_wt_lo[9 * CDIM * CDIM];

// ======================= helpers =============================
__device__ __forceinline__ uint32_t smem_to_u32(const void* p) {
    uint32_t a;
    asm("{ .reg .u64 t; cvta.to.shared.u64 t, %1; cvt.u32.u64 %0, t; }"
        : "=r"(a) : "l"(p));
    return a;
}
#define SMEM_SWIZZLE_128B(off) ((off) ^ (((off) >> 3) & 0x70))

#define CP16(dst, src, vsz) \
    asm volatile("cp.async.cg.shared.global [%0], [%1], 16, %2;" \
                 :: "r"((uint32_t)(dst)), "l"(src), "r"(vsz))
#define CP_COMMIT() asm volatile("cp.async.commit_group;" ::: "memory")
#define CP_WAIT(n)  asm volatile("cp.async.wait_group %0;" :: "n"(n) : "memory")

__device__ __forceinline__ void ldx4(uint32_t* r, uint32_t addr) {
    asm volatile("ldmatrix.sync.aligned.m8n8.x4.shared.b16 {%0,%1,%2,%3}, [%4];"
                 : "=r"(r[0]), "=r"(r[1]), "=r"(r[2]), "=r"(r[3]) : "r"(addr));
}
__device__ __forceinline__ void ldx4t(uint32_t* r, uint32_t addr) {
    asm volatile("ldmatrix.sync.aligned.m8n8.x4.trans.shared.b16 {%0,%1,%2,%3}, [%4];"
                 : "=r"(r[0]), "=r"(r[1]), "=r"(r[2]), "=r"(r[3]) : "r"(addr));
}
__device__ __forceinline__ void mma16816(float* d, const uint32_t* a,
                                         uint32_t b0, uint32_t b1) {
    asm volatile(
        "mma.sync.aligned.m16n8k16.row.col.f32.bf16.bf16.f32 "
        "{%0,%1,%2,%3}, {%4,%5,%6,%7}, {%8,%9}, {%0,%1,%2,%3};"
        : "+f"(d[0]), "+f"(d[1]), "+f"(d[2]), "+f"(d[3])
        : "r"(a[0]), "r"(a[1]), "r"(a[2]), "r"(a[3]), "r"(b0), "r"(b1));
}
// pack (lo_elem -> low half, hi_elem -> high half)
__device__ __forceinline__ uint32_t packbf(float lo_elem, float hi_elem) {
    uint32_t d;
    asm("cvt.rn.bf16x2.f32 %0, %1, %2;" : "=r"(d) : "f"(hi_elem), "f"(lo_elem));
    return d;
}

// ---- packed f32x2 helpers (FFMA2, used by proj) ----
__device__ __forceinline__ unsigned long long pack2(float lo, float hi) {
    unsigned long long r;
    asm("mov.b64 %0, {%1, %2};" : "=l"(r) : "f"(lo), "f"(hi));
    return r;
}
__device__ __forceinline__ unsigned long long fma2(unsigned long long a,
                                                   unsigned long long b,
                                                   unsigned long long c) {
    unsigned long long d;
    asm("fma.rn.f32x2 %0, %1, %2, %3;" : "=l"(d) : "l"(a), "l"(b), "l"(c));
    return d;
}
__device__ __forceinline__ float2 unpack2(unsigned long long v) {
    float2 f;
    asm("mov.b64 {%0, %1}, %2;" : "=f"(f.x), "=f"(f.y) : "l"(v));
    return f;
}

// ===========================================================================
// convert_W: W[co][ci][k] fp32 -> Wt[k][co][ci] bf16 hi/lo
// ===========================================================================
__global__ __launch_bounds__(256)
void convert_W_kernel(const float* __restrict__ W,
                      __nv_bfloat16* __restrict__ wh, __nv_bfloat16* __restrict__ wl)
{
    __shared__ float ws[9216];
    const int tid = threadIdx.x;
    const int co = blockIdx.x;
    for (int i = tid; i < 9216; i += 256) ws[i] = W[(size_t)co * 9216 + i];
    __syncthreads();
#pragma unroll
    for (int k = 0; k < 9; k++)
        for (int ci = tid; ci < 1024; ci += 256) {
            float f = ws[ci * 9 + k];
            __nv_bfloat16 hi = __float2bfloat16(f);
            float lof = f - __bfloat162float(hi);
            size_t o = ((size_t)k * 1024 + co) * 1024 + ci;
            wh[o] = hi;
            wl[o] = __float2bfloat16(lof);
        }
}

// ===========================================================================
// convert_x: x[b][ci][p] fp32 -> xt[b][p][ci] bf16 hi/lo (transpose + split)
// ===========================================================================
__global__ __launch_bounds__(256)
void convert_x_kernel(const float* __restrict__ x,
                      __nv_bfloat16* __restrict__ xh, __nv_bfloat16* __restrict__ xl)
{
    __shared__ float ts[32][33];
    const int b = blockIdx.z, ci0 = blockIdx.x * 32, p0 = blockIdx.y * 32;
    const int tx = threadIdx.x, ty = threadIdx.y;
#pragma unroll
    for (int r = 0; r < 4; r++)
        ts[ty + 8 * r][tx] = x[((size_t)b * 1024 + ci0 + ty + 8 * r) * 1024 + p0 + tx];
    __syncthreads();
#pragma unroll
    for (int r = 0; r < 4; r++) {
        int pl = ty + 8 * r;
        float f = ts[tx][pl];
        __nv_bfloat16 hi = __float2bfloat16(f);
        float lof = f - __bfloat162float(hi);
        size_t o = ((size_t)b * 1024 + p0 + pl) * 1024 + ci0 + tx;
        xh[o] = hi;
        xl[o] = __float2bfloat16(lof);
    }
}

// ===========================================================================
// conv_mma: 3x3 conv implicit GEMM, bf16x3 split, fp32 accum.
// Epilogue writes bf16 hi/lo directly (scale folds in 1/8 for Q).
// ===========================================================================
#define NSTAGE 144
#define STG    65536
#define CONV_SMEM (2 * STG)

__global__ __launch_bounds__(256, 1)
void conv_mma_kernel(const __nv_bfloat16* __restrict__ Ah,
                     const __nv_bfloat16* __restrict__ Al,
                     const __nv_bfloat16* __restrict__ Bh,
                     const __nv_bfloat16* __restrict__ Bl,
                     const float* __restrict__ bias, float scale,
                     __nv_bfloat16* __restrict__ yh, __nv_bfloat16* __restrict__ yl)
{
    extern __shared__ __align__(1024) char smc[];
    const uint32_t sb = smem_to_u32(smc);
    const int tid = threadIdx.x;
    const int wid = tid >> 5, lane = tid & 31;
    const int co0  = blockIdx.x * 128;
    const int pos0 = blockIdx.y * 128;
    const int b    = blockIdx.z;
    const int co_w  = (wid & 1) * 64;
    const int pos_w = (wid >> 1) * 32;

    float acc[4][4][4];
#pragma unroll
    for (int i = 0; i < 4; i++)
#pragma unroll
        for (int j = 0; j < 4; j++)
#pragma unroll
            for (int k = 0; k < 4; k++) acc[i][j][k] = 0.f;

    auto load_stage = [&](int s) {
        const int buf = s & 1;
        const int tap = s >> 4, chunk = s & 15;
        const int ci0 = chunk * 64;
        const int dy = tap / 3 - 1, dx = tap % 3 - 1;
        const int shift = dy * 32 + dx;
        const uint32_t dbase = sb + buf * STG;

        const __nv_bfloat16* ah = Ah + ((size_t)tap * 1024 + co0) * 1024 + ci0;
        const __nv_bfloat16* al = Al + ((size_t)tap * 1024 + co0) * 1024 + ci0;
#pragma unroll
        for (int it = 0; it < 4; it++) {
            int idx = tid + it * 256;
            int r = idx >> 3, seg = idx & 7;
            uint32_t d = SMEM_SWIZZLE_128B(r * 128 + seg * 16);
            CP16(dbase + d,         ah + (size_t)r * 1024 + seg * 8, 16);
            CP16(dbase + 16384 + d, al + (size_t)r * 1024 + seg * 8, 16);
        }
        const __nv_bfloat16* bh = Bh + (size_t)b * 1048576 + ci0;
        const __nv_bfloat16* bl = Bl + (size_t)b * 1048576 + ci0;
#pragma unroll
        for (int it = 0; it < 4; it++) {
            int idx = tid + it * 256;
            int r = idx >> 3, seg = idx & 7;
            int p = pos0 + r;
            int ri = (p >> 5) + dy, cj = (p & 31) + dx;
            bool ok = ((unsigned)ri < 32u) && ((unsigned)cj < 32u);
            int vs = ok ? 16 : 0;
            size_t off = ok ? ((size_t)(p + shift) * 1024 + seg * 8) : 0;
            uint32_t d = SMEM_SWIZZLE_128B(r * 128 + seg * 16);
            CP16(dbase + 32768 + d, bh + off, vs);
            CP16(dbase + 49152 + d, bl + off, vs);
        }
    };

    load_stage(0);
    CP_COMMIT();

    const int lr = lane & 15, lk = lane >> 4;

    for (int s = 0; s < NSTAGE; s++) {
        if (s + 1 < NSTAGE) { load_stage(s + 1); CP_COMMIT(); CP_WAIT(1); }
        else                { CP_WAIT(0); }
        __syncthreads();

        const uint32_t bufb = sb + (s & 1) * STG;
#pragma unroll
        for (int ks = 0; ks < 4; ks++) {
            const uint32_t colb = ks * 32 + lk * 16;
            uint32_t a[4][4], bb[2][4];

#pragma unroll
            for (int mt = 0; mt < 4; mt++)
                ldx4(a[mt], bufb + SMEM_SWIZZLE_128B((co_w + mt * 16 + lr) * 128 + colb));
#pragma unroll
            for (int nt = 0; nt < 2; nt++)
                ldx4(bb[nt], bufb + 32768 + SMEM_SWIZZLE_128B((pos_w + nt * 16 + lr) * 128 + colb));
#pragma unroll
            for (int mt = 0; mt < 4; mt++)
#pragma unroll
                for (int nt = 0; nt < 2; nt++) {
                    mma16816(acc[mt][nt * 2],     a[mt], bb[nt][0], bb[nt][2]);
                    mma16816(acc[mt][nt * 2 + 1], a[mt], bb[nt][1], bb[nt][3]);
                }

#pragma unroll
            for (int nt = 0; nt < 2; nt++)
                ldx4(bb[nt], bufb + 49152 + SMEM_SWIZZLE_128B((pos_w + nt * 16 + lr) * 128 + colb));
#pragma unroll
            for (int mt = 0; mt < 4; mt++)
#pragma unroll
                for (int nt = 0; nt < 2; nt++) {
                    mma16816(acc[mt][nt * 2],     a[mt], bb[nt][0], bb[nt][2]);
                    mma16816(acc[mt][nt * 2 + 1], a[mt], bb[nt][1], bb[nt][3]);
                }

#pragma unroll
            for (int mt = 0; mt < 4; mt++)
                ldx4(a[mt], bufb + 16384 + SMEM_SWIZZLE_128B((co_w + mt * 16 + lr) * 128 + colb));
#pragma unroll
            for (int nt = 0; nt < 2; nt++)
                ldx4(bb[nt], bufb + 32768 + SMEM_SWIZZLE_128B((pos_w + nt * 16 + lr) * 128 + colb));
#pragma unroll
            for (int mt = 0; mt < 4; mt++)
#pragma unroll
                for (int nt = 0; nt < 2; nt++) {
                    mma16816(acc[mt][nt * 2],     a[mt], bb[nt][0], bb[nt][2]);
                    mma16816(acc[mt][nt * 2 + 1], a[mt], bb[nt][1], bb[nt][3]);
                }
        }
        __syncthreads();
    }

    // ---- epilogue: (acc + bias) * scale -> bf16 hi/lo ----
    const int lq = lane >> 2, lrm = lane & 3;
#pragma unroll
    for (int mt = 0; mt < 4; mt++) {
        int r0c = co0 + co_w + mt * 16 + lq;
        float bv0 = bias[r0c], bv1 = bias[r0c + 8];
        size_t row0 = ((size_t)b * 1024 + r0c) * 1024 + pos0 + pos_w;
        size_t row1 = row0 + (size_t)8 * 1024;
#pragma unroll
        for (int j = 0; j < 4; j++) {
            int pofs = j * 8 + lrm * 2;
            float v0 = (acc[mt][j][0] + bv0) * scale;
            float v1 = (acc[mt][j][1] + bv0) * scale;
            float v2 = (acc[mt][j][2] + bv1) * scale;
            float v3 = (acc[mt][j][3] + bv1) * scale;
            __nv_bfloat162 h01, h23, l01, l23;
            h01.x = __float2bfloat16(v0); h01.y = __float2bfloat16(v1);
            h23.x = __float2bfloat16(v2); h23.y = __float2bfloat16(v3);
            l01.x = __float2bfloat16(v0 - __bfloat162float(h01.x));
            l01.y = __float2bfloat16(v1 - __bfloat162float(h01.y));
            l23.x = __float2bfloat16(v2 - __bfloat162float(h23.x));
            l23.y = __float2bfloat16(v3 - __bfloat162float(h23.y));
            *(__nv_bfloat162*)(yh + row0 + pofs) = h01;
            *(__nv_bfloat162*)(yl + row0 + pofs) = l01;
            *(__nv_bfloat162*)(yh + row1 + pofs) = h23;
            *(__nv_bfloat162*)(yl + row1 + pofs) = l23;
        }
    }
}

// ===========================================================================
// attn_mma: flash attention on mma.sync. Grid (8 t-tiles, 16 h, 8 b), blk 256.
// CTA: 128 t-rows; warp: 16 rows x full 64-s tile (softmax warp-local).
// smem: Q hi/lo 32K | K/V hi/lo double-buffered 64K = 96K.
// ===========================================================================
#define ATTN_SMEM 98304

__global__ __launch_bounds__(256, 2)
void attn_mma_kernel(const __nv_bfloat16* __restrict__ Qh,
                     const __nv_bfloat16* __restrict__ Ql,
                     const __nv_bfloat16* __restrict__ Kh,
                     const __nv_bfloat16* __restrict__ Kl,
                     const __nv_bfloat16* __restrict__ Vh,
                     const __nv_bfloat16* __restrict__ Vl,
                     const int* __restrict__ mask, float* __restrict__ O)
{
    extern __shared__ __align__(1024) char sma[];
    const uint32_t sb = smem_to_u32(sma);
    const int tid = threadIdx.x;
    const int wid = tid >> 5, lane = tid & 31;
    const int t0 = blockIdx.x * 128;
    const int h  = blockIdx.y;
    const int b  = blockIdx.z;
    const int lr = lane & 15, lk = lane >> 4;
    const int lq = lane >> 2, lc = lane & 3;

    // ---- load Q tile (once): 128 rows x 64 d, hi+lo ----
#pragma unroll
    for (int it = 0; it < 8; it++) {
        int idx = tid + it * 256;            // 0..2047
        int half = it >> 2, i2 = idx & 1023;
        int r = i2 >> 3, seg = i2 & 7;
        const __nv_bfloat16* src = (half ? Ql : Qh) +
            (((size_t)(b * 1024 + t0 + r)) << 10) + h * 64 + seg * 8;
        CP16(sb + half * 16384 + SMEM_SWIZZLE_128B(r * 128 + seg * 16), src, 16);
    }

    auto load_kv = [&](int itr) {
        const int s0r = itr * 64;
        const uint32_t dbase = sb + 32768 + (itr & 1) * 32768;
#pragma unroll
        for (int it = 0; it < 8; it++) {
            int m = it >> 1;                 // 0:Kh 1:Kl 2:Vh 3:Vl
            int i2 = (tid + it * 256) & 511;
            int r = i2 >> 3, seg = i2 & 7;
            const __nv_bfloat16* sp = (m == 0) ? Kh : (m == 1) ? Kl : (m == 2) ? Vh : Vl;
            const __nv_bfloat16* src = sp +
                (((size_t)(b * 1024 + s0r + r)) << 10) + h * 64 + seg * 8;
            CP16(dbase + m * 8192 + SMEM_SWIZZLE_128B(r * 128 + seg * 16), src, 16);
        }
    };

    load_kv(0);
    CP_COMMIT();

    float oacc[8][4];
#pragma unroll
    for (int i = 0; i < 8; i++)
#pragma unroll
        for (int j = 0; j < 4; j++) oacc[i][j] = 0.f;
    float mx0 = -3.0e38f, mx1 = -3.0e38f, lsum0 = 0.f, lsum1 = 0.f;

    const int* mrowb = mask + ((size_t)(b * 1024 + t0 + wid * 16 + lq) << 10) + lc * 2;

    for (int it = 0; it < 16; it++) {
        if (it + 1 < 16) { load_kv(it + 1); CP_COMMIT(); CP_WAIT(1); }
        else             { CP_WAIT(0); }
        __syncthreads();
        const uint32_t kb = sb + 32768 + (it & 1) * 32768;

        // ---- S = Q K^T (bf16x3) ----
        float sacc[8][4];
#pragma unroll
        for (int i = 0; i < 8; i++)
#pragma unroll
            for (int j = 0; j < 4; j++) sacc[i][j] = 0.f;

#pragma unroll
        for (int kc = 0; kc < 4; kc++) {
            const uint32_t colb = kc * 32 + lk * 16;
            uint32_t qh4[4], ql4[4];
            ldx4(qh4, sb + SMEM_SWIZZLE_128B((wid * 16 + lr) * 128 + colb));
            ldx4(ql4, sb + 16384 + SMEM_SWIZZLE_128B((wid * 16 + lr) * 128 + colb));
#pragma unroll
            for (int g = 0; g < 4; g++) {
                uint32_t kh4[4], kl4[4];
                ldx4(kh4, kb + SMEM_SWIZZLE_128B((g * 16 + lr) * 128 + colb));
                ldx4(kl4, kb + 8192 + SMEM_SWIZZLE_128B((g * 16 + lr) * 128 + colb));
                mma16816(sacc[2 * g],     qh4, kh4[0], kh4[2]);
                mma16816(sacc[2 * g + 1], qh4, kh4[1], kh4[3]);
                mma16816(sacc[2 * g],     qh4, kl4[0], kl4[2]);
                mma16816(sacc[2 * g + 1], qh4, kl4[1], kl4[3]);
                mma16816(sacc[2 * g],     ql4, kh4[0], kh4[2]);
                mma16816(sacc[2 * g + 1], ql4, kh4[1], kh4[3]);
            }
        }

        // ---- mask + online softmax (warp-local) ----
        const int* mr0 = mrowb + it * 64;
        const int* mr1 = mr0 + 8 * 1024;
        float rmax0 = -3.0e38f, rmax1 = -3.0e38f;
#pragma unroll
        for (int nt = 0; nt < 8; nt++) {
            int2 mm0 = *(const int2*)(mr0 + nt * 8);
            int2 mm1 = *(const int2*)(mr1 + nt * 8);
            sacc[nt][0] = mm0.x ? sacc[nt][0] : -1e9f;
            sacc[nt][1] = mm0.y ? sacc[nt][1] : -1e9f;
            sacc[nt][2] = mm1.x ? sacc[nt][2] : -1e9f;
            sacc[nt][3] = mm1.y ? sacc[nt][3] : -1e9f;
            rmax0 = fmaxf(rmax0, fmaxf(sacc[nt][0], sacc[nt][1]));
            rmax1 = fmaxf(rmax1, fmaxf(sacc[nt][2], sacc[nt][3]));
        }
        rmax0 = fmaxf(rmax0, __shfl_xor_sync(0xffffffffu, rmax0, 1));
        rmax0 = fmaxf(rmax0, __shfl_xor_sync(0xffffffffu, rmax0, 2));
        rmax1 = fmaxf(rmax1, __shfl_xor_sync(0xffffffffu, rmax1, 1));
        rmax1 = fmaxf(rmax1, __shfl_xor_sync(0xffffffffu, rmax1, 2));
        float mn0 = fmaxf(mx0, rmax0), mn1 = fmaxf(mx1, rmax1);
        float f0 = __expf(mx0 - mn0), f1 = __expf(mx1 - mn1);
        mx0 = mn0; mx1 = mn1;

        float rs0 = 0.f, rs1 = 0.f;
        uint32_t ph01[8], ph23[8], pl01[8], pl23[8];
#pragma unroll
        for (int nt = 0; nt < 8; nt++) {
            float p0 = __expf(sacc[nt][0] - mn0);
            float p1 = __expf(sacc[nt][1] - mn0);
            float p2 = __expf(sacc[nt][2] - mn1);
            float p3 = __expf(sacc[nt][3] - mn1);
            rs0 += p0 + p1; rs1 += p2 + p3;
            uint32_t h01 = packbf(p0, p1);
            uint32_t h23 = packbf(p2, p3);
            ph01[nt] = h01; ph23[nt] = h23;
            float q0 = p0 - __uint_as_float(h01 << 16);
            float q1 = p1 - __uint_as_float(h01 & 0xFFFF0000u);
            float q2 = p2 - __uint_as_float(h23 << 16);
            float q3 = p3 - __uint_as_float(h23 & 0xFFFF0000u);
            pl01[nt] = packbf(q0, q1);
            pl23[nt] = packbf(q2, q3);
        }
        rs0 += __shfl_xor_sync(0xffffffffu, rs0, 1);
        rs0 += __shfl_xor_sync(0xffffffffu, rs0, 2);
        rs1 += __shfl_xor_sync(0xffffffffu, rs1, 1);
        rs1 += __shfl_xor_sync(0xffffffffu, rs1, 2);
        lsum0 = lsum0 * f0 + rs0;
        lsum1 = lsum1 * f1 + rs1;
#pragma unroll
        for (int nt = 0; nt < 8; nt++) {
            oacc[nt][0] *= f0; oacc[nt][1] *= f0;
            oacc[nt][2] *= f1; oacc[nt][3] *= f1;
        }

        // ---- O += P V (P hi/lo x V hi/lo, 3 terms) ----
#pragma unroll
        for (int kc2 = 0; kc2 < 4; kc2++) {
            uint32_t pah[4] = {ph01[2 * kc2], ph23[2 * kc2],
                               ph01[2 * kc2 + 1], ph23[2 * kc2 + 1]};
            uint32_t pal[4] = {pl01[2 * kc2], pl23[2 * kc2],
                               pl01[2 * kc2 + 1], pl23[2 * kc2 + 1]};
#pragma unroll
            for (int dc = 0; dc < 4; dc++) {
                const uint32_t vaddr = (kc2 * 16 + lr) * 128 + dc * 32 + lk * 16;
                uint32_t vh4[4], vl4[4];
                ldx4t(vh4, kb + 16384 + SMEM_SWIZZLE_128B(vaddr));
                ldx4t(vl4, kb + 24576 + SMEM_SWIZZLE_128B(vaddr));
                mma16816(oacc[2 * dc],     pah, vh4[0], vh4[1]);
                mma16816(oacc[2 * dc + 1], pah, vh4[2], vh4[3]);
                mma16816(oacc[2 * dc],     pah, vl4[0], vl4[1]);
                mma16816(oacc[2 * dc + 1], pah, vl4[2], vl4[3]);
                mma16816(oacc[2 * dc],     pal, vh4[0], vh4[1]);
                mma16816(oacc[2 * dc + 1], pal, vh4[2], vh4[3]);
            }
        }
        __syncthreads();
    }

    // ---- epilogue: O / l -> fp32 ----
    const float inv0 = 1.0f / lsum0, inv1 = 1.0f / lsum1;
    const int row0 = t0 + wid * 16 + lq;
    const size_t b0 = (((size_t)(b * 1024 + row0)) << 10) + h * 64 + lc * 2;
    const size_t b1 = b0 + ((size_t)8 << 10);
#pragma unroll
    for (int nt = 0; nt < 8; nt++) {
        *(float2*)(O + b0 + nt * 8) = make_float2(oacc[nt][0] * inv0, oacc[nt][1] * inv0);
        *(float2*)(O + b1 + nt * 8) = make_float2(oacc[nt][2] * inv1, oacc[nt][3] * inv1);
    }
}

// ===========================================================================
// Output projection (FFMA2)
// ===========================================================================
__global__ __launch_bounds__(256, 4)
void proj_kernel(const float* __restrict__ A, const float* __restrict__ Wo,
                 const float* __restrict__ bo, float* __restrict__ out)
{
    __shared__ float As[16][68];
    __shared__ float Bs[16][68];

    const int tid = threadIdx.x;
    const int ty = tid >> 4, tx = tid & 15;
    const int j0 = blockIdx.x * 64;
    const int t0 = blockIdx.y * 64;
    const int b  = blockIdx.z;

    unsigned long long acc2[4][2];
#pragma unroll
    for (int i = 0; i < 4; i++) { acc2[i][0] = 0ull; acc2[i][1] = 0ull; }

    const float* Ab = A + (size_t)b * CDIM * POS;

    for (int i0 = 0; i0 < 1024; i0 += 16) {
        for (int idx = tid; idx < 1024; idx += 256) {
            int r = idx >> 4, kk = idx & 15;
            As[kk][r] = Ab[(size_t)(t0 + r) * 1024 + i0 + kk];
            Bs[kk][r] = Wo[(size_t)(j0 + r) * 1024 + i0 + kk];
        }
        __syncthreads();
#pragma unroll
        for (int kk = 0; kk < 16; kk++) {
            float4 a4 = *(const float4*)(&As[kk][ty * 4]);
            float4 w4 = *(const float4*)(&Bs[kk][tx * 4]);
            unsigned long long w01 = pack2(w4.x, w4.y);
            unsigned long long w23 = pack2(w4.z, w4.w);
            unsigned long long ab;
            ab = pack2(a4.x, a4.x);
            acc2[0][0] = fma2(ab, w01, acc2[0][0]); acc2[0][1] = fma2(ab, w23, acc2[0][1]);
            ab = pack2(a4.y, a4.y);
            acc2[1][0] = fma2(ab, w01, acc2[1][0]); acc2[1][1] = fma2(ab, w23, acc2[1][1]);
            ab = pack2(a4.z, a4.z);
            acc2[2][0] = fma2(ab, w01, acc2[2][0]); acc2[2][1] = fma2(ab, w23, acc2[2][1]);
            ab = pack2(a4.w, a4.w);
            acc2[3][0] = fma2(ab, w01, acc2[3][0]); acc2[3][1] = fma2(ab, w23, acc2[3][1]);
        }
        __syncthreads();
    }

#pragma unroll
    for (int i = 0; i < 4; i++) {
        size_t o = ((size_t)b * CDIM + t0 + ty * 4 + i) * 1024 + j0 + tx * 4;
        float2 u = unpack2(acc2[i][0]);
        float2 w = unpack2(acc2[i][1]);
        out[o + 0] = u.x + bo[j0 + tx * 4 + 0];
        out[o + 1] = u.y + bo[j0 + tx * 4 + 1];
        out[o + 2] = w.x + bo[j0 + tx * 4 + 2];
        out[o + 3] = w.y + bo[j0 + tx * 4 + 3];
    }
}

// ===========================================================================
extern "C" void kernel_launch(void* const* d_in, const int* in_sizes, int n_in,
                              void* d_out, int out_size)
{
    const float* q    = (const float*)d_in[0];
    const float* k    = (const float*)d_in[1];
    const float* v    = (const float*)d_in[2];
    const float* Wq   = (const float*)d_in[3];
    const float* bq   = (const float*)d_in[4];
    const float* Wk   = (const float*)d_in[5];
    const float* bk   = (const float*)d_in[6];
    const float* Wv   = (const float*)d_in[7];
    const float* bv   = (const float*)d_in[8];
    const float* Wo   = (const float*)d_in[9];
    const float* bo   = (const float*)d_in[10];
    const int*   mask = (const int*)d_in[11];
    float* out = (float*)d_out;

    float* Oc;
    cudaGetSymbolAddress((void**)&Oc, g_Oc);
    __nv_bfloat16 *xh, *xl, *wh, *wl;
    cudaGetSymbolAddress((void**)&xh, g_xt_hi);
    cudaGetSymbolAddress((void**)&xl, g_xt_lo);
    cudaGetSymbolAddress((void**)&wh, g_wt_hi);
    cudaGetSymbolAddress((void**)&wl, g_wt_lo);
    __nv_bfloat16 *qh, *ql, *kh, *kl, *vh, *vl;
    cudaGetSymbolAddress((void**)&qh, g_qh);
    cudaGetSymbolAddress((void**)&ql, g_ql);
    cudaGetSymbolAddress((void**)&kh, g_kh);
    cudaGetSymbolAddress((void**)&kl, g_kl);
    cudaGetSymbolAddress((void**)&vh, g_vh);
    cudaGetSymbolAddress((void**)&vl, g_vl);

    cudaFuncSetAttribute(conv_mma_kernel, cudaFuncAttributeMaxDynamicSharedMemorySize,
                         CONV_SMEM);
    cudaFuncSetAttribute(attn_mma_kernel, cudaFuncAttributeMaxDynamicSharedMemorySize,
                         ATTN_SMEM);

    const float* xin[3] = {q, k, v};
    const float* Win[3] = {Wq, Wk, Wv};
    const float* bin[3] = {bq, bk, bv};
    __nv_bfloat16* oh[3] = {qh, kh, vh};
    __nv_bfloat16* ol[3] = {ql, kl, vl};
    const float scales[3] = {0.125f, 1.0f, 1.0f};

    dim3 cxg(32, 32, 8), cxb(32, 8);
    dim3 mg(8, 8, 8);
    for (int i = 0; i < 3; i++) {
        convert_W_kernel<<<1024, 256>>>(Win[i], wh, wl);
        convert_x_kernel<<<cxg, cxb>>>(xin[i], xh, xl);
        conv_mma_kernel<<<mg, 256, CONV_SMEM>>>(wh, wl, xh, xl, bin[i], scales[i],
                                                oh[i], ol[i]);
    }

    dim3 ag(8, 16, 8);
    attn_mma_kernel<<<ag, 256, ATTN_SMEM>>>(qh, ql, kh, kl, vh, vl, mask, Oc);

    dim3 pgrid(16, 16, 8);
    proj_kernel<<<pgrid, 256>>>(Oc, Wo, bo, out);
}